// round 16
// baseline (speedup 1.0000x reference)
#include <cuda_runtime.h>
#include <math.h>

// Problem constants (B=4, S=4096, D=2048, E=8, K=2)
#define NTOK    16384
#define DIM     2048
#define NEXP    8
#define NASSIGN (NTOK*2)       // 32768
#define CAP     5120           // int(NTOK*2/8 * 1.25)
#define NTASK   (NTOK/4)       // 4096 tasks of 4 contiguous tokens
#define NBLK    152            // persistent, 1 block per SM
#define THREADS 512            // warp 15 = producer, warps 0-14 consumers
#define NCONS   15
#define RING    4              // 4 stages x 32 KB
#define ROWB    (DIM*4)        // 8 KB per token row
#define TASKB   (4*ROWB)       // 32 KB per task (contiguous in gmem)
#define W_BYTES (NEXP*DIM*4)   // 64 KB
#define SMEM_DYN (W_BYTES + RING*TASKB)   // 192 KB

// Output layout (float32): [0,32768) indices | [32768,65536) weights |
// [65536] loss | [65537,98305) mask

__device__ int      g_cnt[NEXP];
__device__ float    g_probsum[NEXP];
__device__ unsigned g_done;
__device__ unsigned g_ticket;
__device__ unsigned long long g_bucket[NEXP][NASSIGN];

__device__ __forceinline__ void ffma2(unsigned long long& d,
                                      unsigned long long a,
                                      unsigned long long b) {
    asm("fma.rn.f32x2 %0, %1, %2, %0;" : "+l"(d) : "l"(a), "l"(b));
}
__device__ __forceinline__ float unpack_sum(unsigned long long v) {
    unsigned lo, hi;
    asm("mov.b64 {%0, %1}, %2;" : "=r"(lo), "=r"(hi) : "l"(v));
    return __uint_as_float(lo) + __uint_as_float(hi);
}
__device__ __forceinline__ unsigned smem_u32(const void* p) {
    return (unsigned)__cvta_generic_to_shared(p);
}
__device__ __forceinline__ void mbar_init(unsigned mb, unsigned cnt) {
    asm volatile("mbarrier.init.shared.b64 [%0], %1;" :: "r"(mb), "r"(cnt) : "memory");
}
__device__ __forceinline__ void mbar_expect_tx(unsigned mb, unsigned bytes) {
    asm volatile("mbarrier.arrive.expect_tx.shared.b64 _, [%0], %1;"
                 :: "r"(mb), "r"(bytes) : "memory");
}
__device__ __forceinline__ void mbar_arrive(unsigned mb) {
    asm volatile("mbarrier.arrive.shared.b64 _, [%0];" :: "r"(mb) : "memory");
}
__device__ __forceinline__ void mbar_wait(unsigned mb, unsigned parity) {
    asm volatile(
        "{\n\t.reg .pred P;\n\t"
        "W_%=:\n\t"
        "mbarrier.try_wait.parity.acquire.cta.shared::cta.b64 P, [%0], %1, 0x989680;\n\t"
        "@P bra D_%=;\n\t"
        "bra W_%=;\n\t"
        "D_%=:\n\t}"
        :: "r"(mb), "r"(parity) : "memory");
}
// Bulk async copy gmem->smem (SASS: UBLKCP.S.G); completion via mbarrier tx.
__device__ __forceinline__ void bulk_g2s(unsigned dst, const void* src,
                                         unsigned bytes, unsigned mb) {
    asm volatile(
        "cp.async.bulk.shared::cluster.global.mbarrier::complete_tx::bytes "
        "[%0], [%1], %2, [%3];"
        :: "r"(dst), "l"(src), "r"(bytes), "r"(mb) : "memory");
}

// Persistent TMA-fed kernel. Producer thread streams whole 32 KB tasks
// (4 contiguous token rows) into a 4-stage ring with one mbarrier-tracked
// bulk copy set per stage. 15 consumer warps claim stages via a block-local
// sequence ticket; a per-stage turn word serializes same-stage claims so the
// 1-bit mbarrier parity is unambiguous. No __syncthreads in streaming path.
// LAST arriving block computes loss + (rare) capacity drop + resets scratch.
__global__ __launch_bounds__(THREADS, 1)
void router_main(const float* __restrict__ x,
                 const float* __restrict__ wg,
                 float* __restrict__ out) {
    extern __shared__ float sw[];             // w 64 KB; ring after
    __shared__ __align__(8) unsigned long long mb_full[RING];
    __shared__ __align__(8) unsigned long long mb_empty[RING];
    __shared__ int          s_meta[RING];     // task id, -1 = poison
    __shared__ volatile int s_turn[RING];     // consumption cycle per stage
    __shared__ int          s_seq;            // block-local sequence ticket
    __shared__ float        s_prob[NEXP];
    __shared__ int          s_last;

    const int tid  = threadIdx.x;
    const int warp = tid >> 5;
    const int lane = tid & 31;
    if (tid < NEXP) s_prob[tid] = 0.0f;
    if (tid == 0)   s_seq = 0;
    if (tid < RING) {
        mbar_init(smem_u32((const void*)&mb_full[tid]), 1);
        mbar_init(smem_u32((const void*)&mb_empty[tid]), 1);
        s_turn[tid] = 0;
    }

    // stage w_gate once per persistent block
    {
        float4* sw4 = (float4*)sw;
        const float4* wg4 = (const float4*)wg;
        #pragma unroll
        for (int i = tid; i < NEXP * DIM / 4; i += THREADS) sw4[i] = wg4[i];
    }
    __syncthreads();
    asm volatile("fence.proxy.async.shared::cta;" ::: "memory");

    char* ring = (char*)sw + W_BYTES;
    const unsigned ring_u = smem_u32(ring);

    if (warp == NCONS) {
        // ================= PRODUCER (single thread) =================
        if (lane == 0) {
            int pn = 0;                        // fill sequence over stages
            for (;;) {
                int task = (int)atomicAdd(&g_ticket, 1u);
                if (task < NTASK) {
                    const int st = pn & (RING - 1);
                    const unsigned par = 1u ^ ((pn >> 2) & 1);   // fresh=pass
                    mbar_wait(smem_u32((const void*)&mb_empty[st]), par);
                    s_meta[st] = task;
                    unsigned fullmb = smem_u32((const void*)&mb_full[st]);
                    mbar_expect_tx(fullmb, TASKB);
                    const char* src = (const char*)x + (size_t)task * TASKB;
                    #pragma unroll
                    for (int r = 0; r < 4; r++)
                        bulk_g2s(ring_u + st * TASKB + r * ROWB,
                                 src + r * ROWB, ROWB, fullmb);
                    pn++;
                } else {
                    // emit one poison per consumer (these count as fills)
                    for (int k = 0; k < NCONS; k++) {
                        const int st = pn & (RING - 1);
                        const unsigned par = 1u ^ ((pn >> 2) & 1);
                        mbar_wait(smem_u32((const void*)&mb_empty[st]), par);
                        s_meta[st] = -1;
                        mbar_arrive(smem_u32((const void*)&mb_full[st]));
                        pn++;
                    }
                    break;
                }
            }
        }
    } else {
        // ================= CONSUMERS (15 warps) =================
        const ulonglong2* sw2 = (const ulonglong2*)sw;
        const unsigned lane16 = lane * 16;
        for (;;) {
            int n;
            if (lane == 0) n = atomicAdd(&s_seq, 1);
            n = __shfl_sync(0xffffffffu, n, 0);
            const int st = n & (RING - 1);
            const int q  = n >> 2;
            if (lane == 0) {
                while (s_turn[st] != q) __nanosleep(64);   // claim order
                mbar_wait(smem_u32((const void*)&mb_full[st]), (unsigned)(q & 1));
            }
            __syncwarp();
            const int task = s_meta[st];
            if (task < 0) {
                __syncwarp();
                if (lane == 0) {
                    s_turn[st] = q + 1;
                    mbar_arrive(smem_u32((const void*)&mb_empty[st]));
                }
                break;
            }

            const char* buf = ring + st * TASKB;
            unsigned long long acc[4][NEXP];
            #pragma unroll
            for (int t = 0; t < 4; t++)
                #pragma unroll
                for (int e = 0; e < NEXP; e++) acc[t][e] = 0ull;

            #pragma unroll 4
            for (int c = 0; c < 16; c++) {
                ulonglong2 xv0 = *(const ulonglong2*)(buf + 0 * ROWB + c * 512 + lane16);
                ulonglong2 xv1 = *(const ulonglong2*)(buf + 1 * ROWB + c * 512 + lane16);
                ulonglong2 xv2 = *(const ulonglong2*)(buf + 2 * ROWB + c * 512 + lane16);
                ulonglong2 xv3 = *(const ulonglong2*)(buf + 3 * ROWB + c * 512 + lane16);
                const int cc = c * 32 + lane;
                #pragma unroll
                for (int e = 0; e < NEXP; e++) {
                    ulonglong2 wv = sw2[e * (DIM / 4) + cc];
                    ffma2(acc[0][e], xv0.x, wv.x); ffma2(acc[0][e], xv0.y, wv.y);
                    ffma2(acc[1][e], xv1.x, wv.x); ffma2(acc[1][e], xv1.y, wv.y);
                    ffma2(acc[2][e], xv2.x, wv.x); ffma2(acc[2][e], xv2.y, wv.y);
                    ffma2(acc[3][e], xv3.x, wv.x); ffma2(acc[3][e], xv3.y, wv.y);
                }
            }
            __syncwarp();                        // reads done before release
            if (lane == 0) {
                s_turn[st] = q + 1;
                mbar_arrive(smem_u32((const void*)&mb_empty[st]));
            }

            // collapse + butterfly -> lanes 0-3 hold full logits
            float logit[4][NEXP];
            #pragma unroll
            for (int t = 0; t < 4; t++)
                #pragma unroll
                for (int e = 0; e < NEXP; e++) {
                    float v = unpack_sum(acc[t][e]);
                    v += __shfl_xor_sync(0xffffffffu, v, 16);
                    v += __shfl_xor_sync(0xffffffffu, v, 8);
                    v += __shfl_xor_sync(0xffffffffu, v, 4);
                    v += __shfl_xor_sync(0xffffffffu, v, 2);
                    v += __shfl_xor_sync(0xffffffffu, v, 1);
                    logit[t][e] = v;
                }

            if (lane < 4) {
                int token = task * 4 + lane;
                float p[NEXP];
                float m = logit[lane][0];
                #pragma unroll
                for (int e = 1; e < NEXP; e++) m = fmaxf(m, logit[lane][e]);
                float s = 0.0f;
                #pragma unroll
                for (int e = 0; e < NEXP; e++) { p[e] = expf(logit[lane][e] - m); s += p[e]; }
                float inv = 1.0f / s;
                #pragma unroll
                for (int e = 0; e < NEXP; e++) p[e] *= inv;

                int i1 = 0; float b1 = p[0];
                #pragma unroll
                for (int e = 1; e < NEXP; e++) if (p[e] > b1) { b1 = p[e]; i1 = e; }
                int i2 = -1; float b2 = -1.0f;
                #pragma unroll
                for (int e = 0; e < NEXP; e++) if (e != i1 && p[e] > b2) { b2 = p[e]; i2 = e; }

                float ssum = b1 + b2;
                float w1 = b1 / ssum, w2 = b2 / ssum;

                int n0 = token * 2;
                out[n0]     = (float)i1;
                out[n0 + 1] = (float)i2;
                out[NASSIGN + n0]     = w1;
                out[NASSIGN + n0 + 1] = w2;
                out[2 * NASSIGN + 1 + n0]     = 1.0f;
                out[2 * NASSIGN + 1 + n0 + 1] = 1.0f;

                int s1 = atomicAdd(&g_cnt[i1], 1);
                g_bucket[i1][s1] = ((unsigned long long)__float_as_uint(w1) << 32) |
                                   (unsigned)(~(unsigned)n0);
                int s2 = atomicAdd(&g_cnt[i2], 1);
                g_bucket[i2][s2] = ((unsigned long long)__float_as_uint(w2) << 32) |
                                   (unsigned)(~(unsigned)(n0 + 1));

                #pragma unroll
                for (int e = 0; e < NEXP; e++) atomicAdd(&s_prob[e], p[e]);
            }
        }
    }

    // all warps converge
    __syncthreads();
    if (tid < NEXP) atomicAdd(&g_probsum[tid], s_prob[tid]);
    __syncthreads();

    if (tid == 0) {
        __threadfence();
        unsigned old = atomicAdd(&g_done, 1u);
        s_last = (old == (unsigned)(gridDim.x - 1)) ? 1 : 0;
    }
    __syncthreads();
    if (!s_last) return;

    __shared__ int cnt[NEXP];
    if (tid < NEXP) cnt[tid] = __ldcg(&g_cnt[tid]);
    __syncthreads();

    if (tid == 0) {
        float imp[NEXP], imps = 0.0f;
        #pragma unroll
        for (int e = 0; e < NEXP; e++) { imp[e] = __ldcg(&g_probsum[e]); imps += imp[e]; }
        float loss = 0.0f;
        #pragma unroll
        for (int e = 0; e < NEXP; e++)
            loss += (imp[e] / imps) * ((float)cnt[e] / (float)NASSIGN);
        out[2 * NASSIGN] = (float)NEXP * loss;
    }

    // Capacity drop (rank = #{j: key > key_i}; keep iff rank < CAP). Matches
    // lexsort((-w, expert)) with flat-index tiebreak; rarely triggers
    // (expected per-expert count ~4096 << 5120).
    for (int e = 0; e < NEXP; e++) {
        int c = cnt[e];
        if (c <= CAP) continue;
        for (int i = tid; i < c; i += blockDim.x) {
            unsigned long long ki = __ldcg(&g_bucket[e][i]);
            int rank = 0;
            for (int j = 0; j < c; j++)
                rank += (__ldcg(&g_bucket[e][j]) > ki) ? 1 : 0;
            if (rank >= CAP) {
                unsigned nn = ~(unsigned)(ki & 0xffffffffull);
                out[2 * NASSIGN + 1 + nn] = 0.0f;
            }
        }
    }
    __syncthreads();

    if (tid < NEXP) { g_cnt[tid] = 0; g_probsum[tid] = 0.0f; }
    if (tid == 0)   { g_done = 0u; g_ticket = 0u; __threadfence(); }
}

extern "C" void kernel_launch(void* const* d_in, const int* in_sizes, int n_in,
                              void* d_out, int out_size) {
    const float* x  = (const float*)d_in[0];
    const float* wg = (const float*)d_in[1];
    float* out = (float*)d_out;
    (void)in_sizes; (void)n_in; (void)out_size;

    cudaFuncSetAttribute(router_main, cudaFuncAttributeMaxDynamicSharedMemorySize,
                         SMEM_DYN);

    router_main<<<NBLK, THREADS, SMEM_DYN>>>(x, wg, out);
}

// round 17
// speedup vs baseline: 2.0378x; 2.0378x over previous
#include <cuda_runtime.h>
#include <math.h>

// Problem constants (B=4, S=4096, D=2048, E=8, K=2)
#define NTOK    16384
#define DIM     2048
#define NEXP    8
#define NASSIGN (NTOK*2)       // 32768
#define CAP     5120           // int(NTOK*2/8 * 1.25)
#define NPAIR_T (NTOK/2)       // 8192 token pairs
#define NBLK    296            // persistent: 2 blocks per SM
#define W_BYTES (NEXP*DIM*4)   // 64 KB

// Output layout (float32): [0,32768) indices | [32768,65536) weights |
// [65536] loss | [65537,98305) mask

// Scratch: __device__ globals (zero-init at load; last block resets so every
// graph replay sees zeros).
__device__ int      g_cnt[NEXP];
__device__ float    g_probsum[NEXP];
__device__ unsigned g_done;
__device__ unsigned g_ticket;
__device__ unsigned long long g_bucket[NEXP][NASSIGN];

// Packed fp32x2 FMA (Blackwell): d = a*b + d on two f32 lanes (dim pairs).
__device__ __forceinline__ void ffma2(unsigned long long& d,
                                      unsigned long long a,
                                      unsigned long long b) {
    asm("fma.rn.f32x2 %0, %1, %2, %0;" : "+l"(d) : "l"(a), "l"(b));
}
__device__ __forceinline__ float unpack_sum(unsigned long long v) {
    unsigned lo, hi;
    asm("mov.b64 {%0, %1}, %2;" : "=r"(lo), "=r"(hi) : "l"(v));
    return __uint_as_float(lo) + __uint_as_float(hi);
}
// Warp-collective ticket grab (lane 0 atomics, broadcast).
__device__ __forceinline__ int grab_pair(int lane) {
    int t = 0;
    if (lane == 0) t = (int)atomicAdd(&g_ticket, 1u);
    return __shfl_sync(0xffffffffu, t, 0);
}

// Persistent fused kernel. Each warp independently pulls token PAIRS from a
// global ticket (next grab prefetched under compute). Per half-row it batches
// 16 LDG.128 (8 KB in flight per warp) before the FFMA2/LDS block.
// LAST arriving block computes loss + (rare) capacity drop + resets scratch.
__global__ __launch_bounds__(256, 2)
void router_main(const float* __restrict__ x,
                 const float* __restrict__ wg,
                 float* __restrict__ out) {
    extern __shared__ float sw[];              // 8*2048 f32 = 64 KB
    __shared__ float s_prob[NEXP];
    __shared__ int   s_last;

    const int tid  = threadIdx.x;
    const int lane = tid & 31;
    if (tid < NEXP) s_prob[tid] = 0.0f;

    // stage w_gate into shared ONCE per persistent block
    {
        float4* sw4 = (float4*)sw;
        const float4* wg4 = (const float4*)wg;
        #pragma unroll
        for (int i = tid; i < NEXP * DIM / 4; i += 256) sw4[i] = wg4[i];
    }
    __syncthreads();
    const ulonglong2* sw2 = (const ulonglong2*)sw;

    int pair = grab_pair(lane);
    while (pair < NPAIR_T) {
        const int tok0 = pair * 2;
        const ulonglong2* xr0 = (const ulonglong2*)(x + (size_t)tok0 * DIM);
        const ulonglong2* xr1 = (const ulonglong2*)(x + (size_t)(tok0 + 1) * DIM);

        unsigned long long acc[2][NEXP];
        #pragma unroll
        for (int t = 0; t < 2; t++)
            #pragma unroll
            for (int e = 0; e < NEXP; e++) acc[t][e] = 0ull;

        int next = -1;
        #pragma unroll
        for (int h = 0; h < 2; h++) {
            // batch 16 LDG.128 (two rows x 8 chunks) into registers
            ulonglong2 xa[8], xb[8];
            #pragma unroll
            for (int i = 0; i < 8; i++) {
                int c = (h * 8 + i) * 32 + lane;
                xa[i] = xr0[c];
                xb[i] = xr1[c];
            }
            if (h == 0) next = grab_pair(lane);   // hide ticket latency

            #pragma unroll
            for (int i = 0; i < 8; i++) {
                int c = (h * 8 + i) * 32 + lane;
                #pragma unroll
                for (int e = 0; e < NEXP; e++) {
                    ulonglong2 wv = sw2[e * (DIM / 4) + c];
                    ffma2(acc[0][e], xa[i].x, wv.x); ffma2(acc[0][e], xa[i].y, wv.y);
                    ffma2(acc[1][e], xb[i].x, wv.x); ffma2(acc[1][e], xb[i].y, wv.y);
                }
            }
        }

        // Collapse f32x2 halves, butterfly so lanes 0-1 hold full logits.
        float logit[2][NEXP];
        #pragma unroll
        for (int t = 0; t < 2; t++)
            #pragma unroll
            for (int e = 0; e < NEXP; e++) {
                float v = unpack_sum(acc[t][e]);
                v += __shfl_xor_sync(0xffffffffu, v, 16);
                v += __shfl_xor_sync(0xffffffffu, v, 8);
                v += __shfl_xor_sync(0xffffffffu, v, 4);
                v += __shfl_xor_sync(0xffffffffu, v, 2);
                v += __shfl_xor_sync(0xffffffffu, v, 1);
                logit[t][e] = v;
            }

        if (lane < 2) {
            int token = tok0 + lane;
            float p[NEXP];
            float m = logit[lane][0];
            #pragma unroll
            for (int e = 1; e < NEXP; e++) m = fmaxf(m, logit[lane][e]);
            float s = 0.0f;
            #pragma unroll
            for (int e = 0; e < NEXP; e++) { p[e] = expf(logit[lane][e] - m); s += p[e]; }
            float inv = 1.0f / s;
            #pragma unroll
            for (int e = 0; e < NEXP; e++) p[e] *= inv;

            // top-2, ties -> lowest index
            int i1 = 0; float b1 = p[0];
            #pragma unroll
            for (int e = 1; e < NEXP; e++) if (p[e] > b1) { b1 = p[e]; i1 = e; }
            int i2 = -1; float b2 = -1.0f;
            #pragma unroll
            for (int e = 0; e < NEXP; e++) if (e != i1 && p[e] > b2) { b2 = p[e]; i2 = e; }

            float ssum = b1 + b2;
            float w1 = b1 / ssum, w2 = b2 / ssum;

            int n0 = token * 2;
            out[n0]     = (float)i1;
            out[n0 + 1] = (float)i2;
            out[NASSIGN + n0]     = w1;
            out[NASSIGN + n0 + 1] = w2;
            out[2 * NASSIGN + 1 + n0]     = 1.0f;
            out[2 * NASSIGN + 1 + n0 + 1] = 1.0f;

            // per-expert bucket append; keys order-independent
            int s1 = atomicAdd(&g_cnt[i1], 1);
            g_bucket[i1][s1] = ((unsigned long long)__float_as_uint(w1) << 32) |
                               (unsigned)(~(unsigned)n0);
            int s2 = atomicAdd(&g_cnt[i2], 1);
            g_bucket[i2][s2] = ((unsigned long long)__float_as_uint(w2) << 32) |
                               (unsigned)(~(unsigned)(n0 + 1));

            #pragma unroll
            for (int e = 0; e < NEXP; e++) atomicAdd(&s_prob[e], p[e]);
        }
        pair = next;
    }

    // flush block-accumulated prob sums
    __syncthreads();
    if (tid < NEXP) atomicAdd(&g_probsum[tid], s_prob[tid]);
    __syncthreads();

    // ---- arrival counter: last block finalizes ----
    if (tid == 0) {
        __threadfence();
        unsigned old = atomicAdd(&g_done, 1u);
        s_last = (old == (unsigned)(gridDim.x - 1)) ? 1 : 0;
    }
    __syncthreads();
    if (!s_last) return;

    __shared__ int cnt[NEXP];
    if (tid < NEXP) cnt[tid] = __ldcg(&g_cnt[tid]);
    __syncthreads();

    if (tid == 0) {
        float imp[NEXP], imps = 0.0f;
        #pragma unroll
        for (int e = 0; e < NEXP; e++) { imp[e] = __ldcg(&g_probsum[e]); imps += imp[e]; }
        float loss = 0.0f;
        #pragma unroll
        for (int e = 0; e < NEXP; e++)
            loss += (imp[e] / imps) * ((float)cnt[e] / (float)NASSIGN);
        out[2 * NASSIGN] = (float)NEXP * loss;
    }

    // Capacity drop (rank = #{j: key > key_i}; keep iff rank < CAP). Matches
    // lexsort((-w, expert)) with flat-index tiebreak; rarely triggers
    // (expected per-expert count ~4096 << 5120).
    for (int e = 0; e < NEXP; e++) {
        int c = cnt[e];
        if (c <= CAP) continue;
        for (int i = tid; i < c; i += blockDim.x) {
            unsigned long long ki = __ldcg(&g_bucket[e][i]);
            int rank = 0;
            for (int j = 0; j < c; j++)
                rank += (__ldcg(&g_bucket[e][j]) > ki) ? 1 : 0;
            if (rank >= CAP) {
                unsigned n = ~(unsigned)(ki & 0xffffffffull);
                out[2 * NASSIGN + 1 + n] = 0.0f;
            }
        }
    }
    __syncthreads();

    // reset scratch for the next graph replay
    if (tid < NEXP) { g_cnt[tid] = 0; g_probsum[tid] = 0.0f; }
    if (tid == 0)   { g_done = 0u; g_ticket = 0u; __threadfence(); }
}

extern "C" void kernel_launch(void* const* d_in, const int* in_sizes, int n_in,
                              void* d_out, int out_size) {
    const float* x  = (const float*)d_in[0];
    const float* wg = (const float*)d_in[1];
    float* out = (float*)d_out;
    (void)in_sizes; (void)n_in; (void)out_size;

    cudaFuncSetAttribute(router_main, cudaFuncAttributeMaxDynamicSharedMemorySize,
                         W_BYTES);

    router_main<<<NBLK, 256, W_BYTES>>>(x, wg, out);
}